// round 11
// baseline (speedup 1.0000x reference)
#include <cuda_runtime.h>
#include <stdint.h>

#define IN_F   4096
#define OUT_F  4096
#define RANK_  16
#define MROWS  16384            // 4*4096 flattened rows
#define TH_    0xE6666600u      // bits < TH_  <=>  uniform(bits) < 0.9f (exact)
#define KT     512              // k-tile per k1 block
#define NKT    (IN_F / KT)      // 8 k-tiles
#define BM1    32               // rows per k1 block: 8 warps x 4 rows
#define RB     64               // rows per block (k2)
#define CBT    512              // col-chunk (k2)

typedef unsigned long long u64;

// scratch (allocation-free rule: __device__ globals)
// partial T sums: [ktile][row][rank], summed by k2 while staging
static __device__ float g_Tp[NKT * MROWS * RANK_];   // 8 MB

// ---------- f32x2 helpers ----------
__device__ __forceinline__ u64 pack2f(float lo, float hi) {
    u64 r;
    asm("mov.b64 %0, {%1, %2};" : "=l"(r)
        : "r"(__float_as_uint(lo)), "r"(__float_as_uint(hi)));
    return r;
}
__device__ __forceinline__ void unpack2f(u64 v, float& lo, float& hi) {
    unsigned a, b;
    asm("mov.b64 {%0, %1}, %2;" : "=r"(a), "=r"(b) : "l"(v));
    lo = __uint_as_float(a); hi = __uint_as_float(b);
}
__device__ __forceinline__ u64 ffma2(u64 a, u64 b, u64 c) {
    u64 d;
    asm("fma.rn.f32x2 %0, %1, %2, %3;" : "=l"(d) : "l"(a), "l"(b), "l"(c));
    return d;
}
__device__ __forceinline__ u64 fadd2(u64 a, u64 b) {
    u64 d;
    asm("add.rn.f32x2 %0, %1, %2;" : "=l"(d) : "l"(a), "l"(b));
    return d;
}

// ---------- partitionable-threefry, 4 interleaved instances, NAMED scalars ----------
// JAX (jax_threefry_partitionable=True): counter (0, i), key (0, 42),
// bits32 = o0 ^ o1 of a single threefry2x32-20. Plain adds (ptxas balances pipes).
__device__ __forceinline__ uint4 tf4(unsigned i0, unsigned i1,
                                     unsigned i2, unsigned i3) {
    const unsigned ks1 = 42u, ks2 = 0x1BD11BF0u;  // 0x1BD11BDA ^ 0 ^ 42
    unsigned a0 = 0u, a1 = i0 + ks1;
    unsigned b0 = 0u, b1 = i1 + ks1;
    unsigned c0 = 0u, c1 = i2 + ks1;
    unsigned d0 = 0u, d1 = i3 + ks1;
#define R4(R) { a0 += a1; b0 += b1; c0 += c1; d0 += d1;                    \
                a1 = __funnelshift_l(a1, a1, (R)) ^ a0;                    \
                b1 = __funnelshift_l(b1, b1, (R)) ^ b0;                    \
                c1 = __funnelshift_l(c1, c1, (R)) ^ c0;                    \
                d1 = __funnelshift_l(d1, d1, (R)) ^ d0; }
#define K4(C0, C1) { a0 += (C0); b0 += (C0); c0 += (C0); d0 += (C0);       \
                     a1 += (C1); b1 += (C1); c1 += (C1); d1 += (C1); }
#define K4B(C1)    { a1 += (C1); b1 += (C1); c1 += (C1); d1 += (C1); }
    R4(13) R4(15) R4(26) R4(6)
    K4(ks1, ks2 + 1u)
    R4(17) R4(29) R4(16) R4(24)
    K4(ks2, 2u)                   // ks0 + 2
    R4(13) R4(15) R4(26) R4(6)
    K4B(ks1 + 3u)                 // x0 += ks0(=0) elided
    R4(17) R4(29) R4(16) R4(24)
    K4(ks1, ks2 + 4u)
    R4(13) R4(15) R4(26) R4(6)
    K4(ks2, 5u)                   // ks0 + 5
#undef R4
#undef K4
#undef K4B
    return make_uint4(a0 ^ a1, b0 ^ b1, c0 ^ c1, d0 ^ d1);
}

// ---------- k1: partial T = x[:, kt] @ A[:, kt]^T, barrier-free mainloop ----------
// block = 32 rows x one 512-wide k-tile. A chunk in smem loaded ONCE.
__global__ void __launch_bounds__(256, 2) k1_xa(const float* __restrict__ x,
                                                const float* __restrict__ A) {
    __shared__ u64 At_s2[RANK_ / 2][KT];   // 32 KB, (r even, r odd) pairs

    const int tid  = threadIdx.x;
    const int wid  = tid >> 5;             // 0..7, warp owns rows {4w..4w+3}
    const int lane = tid & 31;
    const int kt   = blockIdx.x & (NKT - 1);
    const int m0   = (blockIdx.x >> 3) * BM1;
    const int k0   = kt * KT;

    // load A chunk once: 16 rows x 512 cols; thread covers 2 cols, all 16 rows
#pragma unroll
    for (int i = 0; i < 2; ++i) {
        int kk = tid + 256 * i;
        const float* ap = A + k0 + kk;
        float v[16];
#pragma unroll
        for (int r = 0; r < 16; ++r) v[r] = ap[(size_t)r * IN_F];
#pragma unroll
        for (int j = 0; j < 8; ++j)
            At_s2[j][kk] = pack2f(v[2 * j], v[2 * j + 1]);
    }
    __syncthreads();   // the only barrier

    u64 acc2[4][8];
#pragma unroll
    for (int mi = 0; mi < 4; ++mi)
#pragma unroll
        for (int rr = 0; rr < 8; ++rr) acc2[mi][rr] = 0ull;

    const float* xr0 = x + (size_t)(m0 + wid * 4) * IN_F + k0 + lane;

#pragma unroll 4
    for (int s = 0; s < KT / 32; ++s) {
        const int k = lane + 32 * s;
        float xv[4];
#pragma unroll
        for (int mi = 0; mi < 4; ++mi)
            xv[mi] = xr0[(size_t)mi * IN_F + 32 * s];   // coalesced LDG.32
        u64 a2[8];
#pragma unroll
        for (int rr = 0; rr < 8; ++rr) a2[rr] = At_s2[rr][k];
#pragma unroll
        for (int mi = 0; mi < 4; ++mi) {
            u64 xx = pack2f(xv[mi], xv[mi]);
#pragma unroll
            for (int rr = 0; rr < 8; ++rr)
                acc2[mi][rr] = ffma2(xx, a2[rr], acc2[mi][rr]);
        }
    }

    // butterfly reduce across 32 k-lanes
#pragma unroll
    for (int off = 16; off > 0; off >>= 1) {
#pragma unroll
        for (int mi = 0; mi < 4; ++mi)
#pragma unroll
            for (int rr = 0; rr < 8; ++rr) {
                u64 o = __shfl_xor_sync(0xffffffffu, acc2[mi][rr], off);
                acc2[mi][rr] = fadd2(acc2[mi][rr], o);
            }
    }
    if (lane < RANK_) {
        const float CMUL = 2.0f / 0.9f;   // scaling / keep, folded into partials
#pragma unroll
        for (int mi = 0; mi < 4; ++mi) {
            float lo, hi;
            unpack2f(acc2[mi][lane >> 1], lo, hi);
            float v = ((lane & 1) ? hi : lo) * CMUL;
            g_Tp[(size_t)kt * MROWS * RANK_ +
                 (size_t)(m0 + wid * 4 + mi) * RANK_ + lane] = v;
        }
    }
}

// ---------- k2: y = dropout( T @ B^T ), sums T partials while staging ----------
__global__ void __launch_bounds__(256, 4) k2_by(const float* __restrict__ B,
                                                float* __restrict__ y) {
    __shared__ u64 B_s[RANK_][CBT / 2];  // 32 KB, col pairs (o even, o odd)
    __shared__ u64 T_s[RB][RANK_];       // 8 KB, (t,t) packed

    const int tid   = threadIdx.x;
    const int cb    = (blockIdx.x & 7) * CBT;           // col tile 0..7
    const int rbase = (blockIdx.x >> 3) * RB;           // row tile

    // stage B slice: thread t owns output cols {cb+2t, cb+2t+1}; their B rows
    // are contiguous 128 bytes -> 8 coalesced float4 loads, zero shuffles.
    {
        const float4* bp = reinterpret_cast<const float4*>(B + (size_t)(cb + 2 * tid) * RANK_);
        float4 r0 = bp[0], r1 = bp[1], r2 = bp[2], r3 = bp[3];   // row o = cb+2t
        float4 s0 = bp[4], s1 = bp[5], s2 = bp[6], s3 = bp[7];   // row o = cb+2t+1
        B_s[ 0][tid] = pack2f(r0.x, s0.x);
        B_s[ 1][tid] = pack2f(r0.y, s0.y);
        B_s[ 2][tid] = pack2f(r0.z, s0.z);
        B_s[ 3][tid] = pack2f(r0.w, s0.w);
        B_s[ 4][tid] = pack2f(r1.x, s1.x);
        B_s[ 5][tid] = pack2f(r1.y, s1.y);
        B_s[ 6][tid] = pack2f(r1.z, s1.z);
        B_s[ 7][tid] = pack2f(r1.w, s1.w);
        B_s[ 8][tid] = pack2f(r2.x, s2.x);
        B_s[ 9][tid] = pack2f(r2.y, s2.y);
        B_s[10][tid] = pack2f(r2.z, s2.z);
        B_s[11][tid] = pack2f(r2.w, s2.w);
        B_s[12][tid] = pack2f(r3.x, s3.x);
        B_s[13][tid] = pack2f(r3.y, s3.y);
        B_s[14][tid] = pack2f(r3.z, s3.z);
        B_s[15][tid] = pack2f(r3.w, s3.w);
    }
    // stage T rows: sum the 8 k-tile partials; thread covers 4 (row,rank) slots
    {
        const float* tp = g_Tp + (size_t)rbase * RANK_ + tid * 4;
        float4 tv = *reinterpret_cast<const float4*>(tp);
#pragma unroll
        for (int ktile = 1; ktile < NKT; ++ktile) {
            float4 p = *reinterpret_cast<const float4*>(
                tp + (size_t)ktile * MROWS * RANK_);
            tv.x += p.x; tv.y += p.y; tv.z += p.z; tv.w += p.w;
        }
        u64* ts = &T_s[0][0];
        ts[tid * 4 + 0] = pack2f(tv.x, tv.x);
        ts[tid * 4 + 1] = pack2f(tv.y, tv.y);
        ts[tid * 4 + 2] = pack2f(tv.z, tv.z);
        ts[tid * 4 + 3] = pack2f(tv.w, tv.w);
    }
    __syncthreads();

    // this thread's B column-pair, held across all rows
    u64 b[RANK_];
#pragma unroll
    for (int r = 0; r < RANK_; ++r) b[r] = B_s[r][tid];

#pragma unroll 1
    for (int q = 0; q < RB; q += 2) {
        u64 accA = 0ull, accB = 0ull;
#pragma unroll
        for (int rp = 0; rp < RANK_ / 2; ++rp) {
            ulonglong2 tA = *reinterpret_cast<const ulonglong2*>(&T_s[q][rp * 2]);
            ulonglong2 tB = *reinterpret_cast<const ulonglong2*>(&T_s[q + 1][rp * 2]);
            accA = ffma2(tA.x, b[rp * 2],     accA);
            accA = ffma2(tA.y, b[rp * 2 + 1], accA);
            accB = ffma2(tB.x, b[rp * 2],     accB);
            accB = ffma2(tB.y, b[rp * 2 + 1], accB);
        }
        float v0, v1, v2, v3;
        unpack2f(accA, v0, v1);
        unpack2f(accB, v2, v3);

        const int m = rbase + q;
        unsigned base_i = (unsigned)m * 4096u + (unsigned)(cb + tid * 2);
        uint4 bb = tf4(base_i, base_i + 1u, base_i + 4096u, base_i + 4097u);
        float o0 = (bb.x < TH_) ? v0 : 0.0f;
        float o1 = (bb.y < TH_) ? v1 : 0.0f;
        float o2 = (bb.z < TH_) ? v2 : 0.0f;
        float o3 = (bb.w < TH_) ? v3 : 0.0f;
        *reinterpret_cast<float2*>(&y[(size_t)m * 4096 + cb + tid * 2]) =
            make_float2(o0, o1);
        *reinterpret_cast<float2*>(&y[(size_t)(m + 1) * 4096 + cb + tid * 2]) =
            make_float2(o2, o3);
    }
}

extern "C" void kernel_launch(void* const* d_in, const int* in_sizes, int n_in,
                              void* d_out, int out_size) {
    const float* x = (const float*)d_in[0];
    const float* A = (const float*)d_in[1];
    const float* B = (const float*)d_in[2];
    float*       y = (float*)d_out;

    k1_xa<<<(MROWS / BM1) * NKT, 256>>>(x, A);
    k2_by<<<(MROWS / RB) * (OUT_F / CBT), 256>>>(B, y);
}

// round 12
// speedup vs baseline: 1.4241x; 1.4241x over previous
#include <cuda_runtime.h>
#include <stdint.h>

#define IN_F   4096
#define OUT_F  4096
#define RANK_  16
#define MROWS  16384            // 4*4096 flattened rows
#define TH_    0xE6666600u      // bits < TH_  <=>  uniform(bits) < 0.9f (exact)
#define KC     128              // k-chunk (k1)
#define NC     (IN_F / KC)      // 32 chunks
#define BM1    32               // rows per block (k1): 8 warps x 4 rows
#define RB     64               // rows per block (k2)
#define CBT    512              // col-chunk (k2)

typedef unsigned long long u64;

// scratch (allocation-free rule: __device__ global)
static __device__ u64 g_T2[MROWS * RANK_];  // T packed as (v,v) f32x2, CMUL folded

// ---------- f32x2 helpers ----------
__device__ __forceinline__ u64 pack2f(float lo, float hi) {
    u64 r;
    asm("mov.b64 %0, {%1, %2};" : "=l"(r)
        : "r"(__float_as_uint(lo)), "r"(__float_as_uint(hi)));
    return r;
}
__device__ __forceinline__ void unpack2f(u64 v, float& lo, float& hi) {
    unsigned a, b;
    asm("mov.b64 {%0, %1}, %2;" : "=r"(a), "=r"(b) : "l"(v));
    lo = __uint_as_float(a); hi = __uint_as_float(b);
}
__device__ __forceinline__ u64 ffma2(u64 a, u64 b, u64 c) {
    u64 d;
    asm("fma.rn.f32x2 %0, %1, %2, %3;" : "=l"(d) : "l"(a), "l"(b), "l"(c));
    return d;
}
__device__ __forceinline__ u64 fadd2(u64 a, u64 b) {
    u64 d;
    asm("add.rn.f32x2 %0, %1, %2;" : "=l"(d) : "l"(a), "l"(b));
    return d;
}
// ---------- cp.async helpers ----------
__device__ __forceinline__ void cp_async16(unsigned smem_addr, const void* gptr) {
    asm volatile("cp.async.ca.shared.global [%0], [%1], 16;\n"
                 :: "r"(smem_addr), "l"(gptr));
}
__device__ __forceinline__ void cp_commit() {
    asm volatile("cp.async.commit_group;\n" ::: "memory");
}
__device__ __forceinline__ void cp_wait0() {
    asm volatile("cp.async.wait_group 0;\n" ::: "memory");
}

// ---------- partitionable-threefry, 4 interleaved instances, NAMED scalars ----------
// JAX (jax_threefry_partitionable=True): counter (0, i), key (0, 42),
// bits32 = o0 ^ o1 of a single threefry2x32-20. Plain adds (ptxas balances pipes).
__device__ __forceinline__ uint4 tf4(unsigned i0, unsigned i1,
                                     unsigned i2, unsigned i3) {
    const unsigned ks1 = 42u, ks2 = 0x1BD11BF0u;  // 0x1BD11BDA ^ 0 ^ 42
    unsigned a0 = 0u, a1 = i0 + ks1;
    unsigned b0 = 0u, b1 = i1 + ks1;
    unsigned c0 = 0u, c1 = i2 + ks1;
    unsigned d0 = 0u, d1 = i3 + ks1;
#define R4(R) { a0 += a1; b0 += b1; c0 += c1; d0 += d1;                    \
                a1 = __funnelshift_l(a1, a1, (R)) ^ a0;                    \
                b1 = __funnelshift_l(b1, b1, (R)) ^ b0;                    \
                c1 = __funnelshift_l(c1, c1, (R)) ^ c0;                    \
                d1 = __funnelshift_l(d1, d1, (R)) ^ d0; }
#define K4(C0, C1) { a0 += (C0); b0 += (C0); c0 += (C0); d0 += (C0);       \
                     a1 += (C1); b1 += (C1); c1 += (C1); d1 += (C1); }
#define K4B(C1)    { a1 += (C1); b1 += (C1); c1 += (C1); d1 += (C1); }
    R4(13) R4(15) R4(26) R4(6)
    K4(ks1, ks2 + 1u)
    R4(17) R4(29) R4(16) R4(24)
    K4(ks2, 2u)                   // ks0 + 2
    R4(13) R4(15) R4(26) R4(6)
    K4B(ks1 + 3u)                 // x0 += ks0(=0) elided
    R4(17) R4(29) R4(16) R4(24)
    K4(ks1, ks2 + 4u)
    R4(13) R4(15) R4(26) R4(6)
    K4(ks2, 5u)                   // ks0 + 5
#undef R4
#undef K4
#undef K4B
    return make_uint4(a0 ^ a1, b0 ^ b1, c0 ^ c1, d0 ^ d1);
}

// ---------- k1: T = x @ A^T, cp.async-pipelined x, double-buffered A ----------
// 256 threads (8 warps), 32 rows/block, 4 rows/warp.
__global__ void __launch_bounds__(256, 2) k1_xa(const float* __restrict__ x,
                                                const float* __restrict__ A) {
    __shared__ float x_s[2][BM1][KC];              // 32 KB
    __shared__ u64   At_s2[2][RANK_ / 2][KC];      // 16 KB

    const int tid  = threadIdx.x;
    const int wid  = tid >> 5;   // 0..7, warp owns rows {4w..4w+3}
    const int lane = tid & 31;
    const int m0   = blockIdx.x * BM1;

    const int ak    = tid & 127;         // A col within chunk
    const int ahalf = tid >> 7;          // 0 -> r 0..7, 1 -> r 8..15

    u64 acc2[4][8];
#pragma unroll
    for (int mi = 0; mi < 4; ++mi)
#pragma unroll
        for (int rr = 0; rr < 8; ++rr) acc2[mi][rr] = 0ull;

    // x cp.async mapping: warp w copies its own rows {4w+mi}; lane covers 16B
    // at float-col lane*4. One chunk row = 512 B = 32 x 16 B.
    const float* xrow[4];
#pragma unroll
    for (int mi = 0; mi < 4; ++mi)
        xrow[mi] = x + (size_t)(m0 + wid * 4 + mi) * IN_F + lane * 4;
    unsigned xs_dst[2];
#pragma unroll
    for (int st = 0; st < 2; ++st)
        xs_dst[st] = (unsigned)__cvta_generic_to_shared(&x_s[st][wid * 4][lane * 4]);

    float ar[8];    // next-chunk A rows

    // prologue: chunk 0
#pragma unroll
    for (int mi = 0; mi < 4; ++mi)
        cp_async16(xs_dst[0] + mi * (KC * 4), xrow[mi]);
    cp_commit();
    {
        const float* ap = A + (size_t)(ahalf * 8) * IN_F + ak;
#pragma unroll
        for (int j = 0; j < 8; ++j) ar[j] = ap[(size_t)j * IN_F];
    }
#pragma unroll
    for (int j = 0; j < 4; ++j)
        At_s2[0][ahalf * 4 + j][ak] = pack2f(ar[2 * j], ar[2 * j + 1]);
    cp_wait0();
    __syncthreads();

#pragma unroll 1
    for (int c = 0; c < NC; ++c) {
        const int buf = c & 1;

        // issue async copies + A prefetch for chunk c+1 (overlap with compute)
        if (c + 1 < NC) {
            const int nbuf = buf ^ 1;
#pragma unroll
            for (int mi = 0; mi < 4; ++mi)
                cp_async16(xs_dst[nbuf] + mi * (KC * 4),
                           xrow[mi] + (c + 1) * KC);
            cp_commit();
            const float* ap = A + (size_t)(ahalf * 8) * IN_F + (c + 1) * KC + ak;
#pragma unroll
            for (int j = 0; j < 8; ++j) ar[j] = ap[(size_t)j * IN_F];
        }

        // compute chunk c
#pragma unroll
        for (int s = 0; s < KC / 32; ++s) {
            int k = lane + 32 * s;
            u64 a2[8];
#pragma unroll
            for (int rr = 0; rr < 8; ++rr) a2[rr] = At_s2[buf][rr][k];
#pragma unroll
            for (int mi = 0; mi < 4; ++mi) {
                float xv = x_s[buf][wid * 4 + mi][k];
                u64 xx = pack2f(xv, xv);
#pragma unroll
                for (int rr = 0; rr < 8; ++rr)
                    acc2[mi][rr] = ffma2(xx, a2[rr], acc2[mi][rr]);
            }
        }

        // stage A chunk c+1, then wait x copies + barrier
        if (c + 1 < NC) {
            const int nbuf = buf ^ 1;
#pragma unroll
            for (int j = 0; j < 4; ++j)
                At_s2[nbuf][ahalf * 4 + j][ak] = pack2f(ar[2 * j], ar[2 * j + 1]);
            cp_wait0();
            __syncthreads();
        }
    }

    // butterfly reduce across 32 k-lanes
#pragma unroll
    for (int off = 16; off > 0; off >>= 1) {
#pragma unroll
        for (int mi = 0; mi < 4; ++mi)
#pragma unroll
            for (int rr = 0; rr < 8; ++rr) {
                u64 o = __shfl_xor_sync(0xffffffffu, acc2[mi][rr], off);
                acc2[mi][rr] = fadd2(acc2[mi][rr], o);
            }
    }
    if (lane < RANK_) {
        const float CMUL = 2.0f / 0.9f;   // scaling / keep, folded into T
#pragma unroll
        for (int mi = 0; mi < 4; ++mi) {
            float lo, hi;
            unpack2f(acc2[mi][lane >> 1], lo, hi);
            float v = ((lane & 1) ? hi : lo) * CMUL;
            g_T2[(size_t)(m0 + wid * 4 + mi) * RANK_ + lane] = pack2f(v, v);
        }
    }
}

// ---------- k2: y = dropout( T @ B^T ), 64 rows/block, ILP-4 threefry ----------
__global__ void __launch_bounds__(256, 4) k2_by(const float* __restrict__ B,
                                                float* __restrict__ y) {
    __shared__ u64 B_s[RANK_][CBT / 2];  // 32 KB, col pairs (o even, o odd)
    __shared__ u64 T_s[RB][RANK_];       // 8 KB, (t,t) packed

    const int tid   = threadIdx.x;
    const int cb    = (blockIdx.x & 7) * CBT;           // col tile 0..7
    const int rbase = (blockIdx.x >> 3) * RB;           // row tile

    // stage B slice: thread t owns output cols {cb+2t, cb+2t+1}; their B rows
    // are contiguous 128 bytes -> 8 coalesced float4 loads, zero shuffles.
    {
        const float4* bp = reinterpret_cast<const float4*>(B + (size_t)(cb + 2 * tid) * RANK_);
        float4 r0 = bp[0], r1 = bp[1], r2 = bp[2], r3 = bp[3];   // row o = cb+2t
        float4 s0 = bp[4], s1 = bp[5], s2 = bp[6], s3 = bp[7];   // row o = cb+2t+1
        B_s[ 0][tid] = pack2f(r0.x, s0.x);
        B_s[ 1][tid] = pack2f(r0.y, s0.y);
        B_s[ 2][tid] = pack2f(r0.z, s0.z);
        B_s[ 3][tid] = pack2f(r0.w, s0.w);
        B_s[ 4][tid] = pack2f(r1.x, s1.x);
        B_s[ 5][tid] = pack2f(r1.y, s1.y);
        B_s[ 6][tid] = pack2f(r1.z, s1.z);
        B_s[ 7][tid] = pack2f(r1.w, s1.w);
        B_s[ 8][tid] = pack2f(r2.x, s2.x);
        B_s[ 9][tid] = pack2f(r2.y, s2.y);
        B_s[10][tid] = pack2f(r2.z, s2.z);
        B_s[11][tid] = pack2f(r2.w, s2.w);
        B_s[12][tid] = pack2f(r3.x, s3.x);
        B_s[13][tid] = pack2f(r3.y, s3.y);
        B_s[14][tid] = pack2f(r3.z, s3.z);
        B_s[15][tid] = pack2f(r3.w, s3.w);
    }
    // stage T rows: 64 rows x 16 = 1024 u64, 4 per thread (2 x LDG.128)
    {
        const ulonglong2* tp = reinterpret_cast<const ulonglong2*>(
            g_T2 + (size_t)rbase * RANK_);
        ulonglong2 t0 = tp[tid * 2];
        ulonglong2 t1 = tp[tid * 2 + 1];
        ulonglong2* ts = reinterpret_cast<ulonglong2*>(&T_s[0][0]);
        ts[tid * 2]     = t0;
        ts[tid * 2 + 1] = t1;
    }
    __syncthreads();

    // this thread's B column-pair, held across all rows
    u64 b[RANK_];
#pragma unroll
    for (int r = 0; r < RANK_; ++r) b[r] = B_s[r][tid];

#pragma unroll 1
    for (int q = 0; q < RB; q += 2) {
        u64 accA = 0ull, accB = 0ull;
#pragma unroll
        for (int rp = 0; rp < RANK_ / 2; ++rp) {
            ulonglong2 tA = *reinterpret_cast<const ulonglong2*>(&T_s[q][rp * 2]);
            ulonglong2 tB = *reinterpret_cast<const ulonglong2*>(&T_s[q + 1][rp * 2]);
            accA = ffma2(tA.x, b[rp * 2],     accA);
            accA = ffma2(tA.y, b[rp * 2 + 1], accA);
            accB = ffma2(tB.x, b[rp * 2],     accB);
            accB = ffma2(tB.y, b[rp * 2 + 1], accB);
        }
        float v0, v1, v2, v3;
        unpack2f(accA, v0, v1);
        unpack2f(accB, v2, v3);

        const int m = rbase + q;
        unsigned base_i = (unsigned)m * 4096u + (unsigned)(cb + tid * 2);
        uint4 bb = tf4(base_i, base_i + 1u, base_i + 4096u, base_i + 4097u);
        float o0 = (bb.x < TH_) ? v0 : 0.0f;
        float o1 = (bb.y < TH_) ? v1 : 0.0f;
        float o2 = (bb.z < TH_) ? v2 : 0.0f;
        float o3 = (bb.w < TH_) ? v3 : 0.0f;
        *reinterpret_cast<float2*>(&y[(size_t)m * 4096 + cb + tid * 2]) =
            make_float2(o0, o1);
        *reinterpret_cast<float2*>(&y[(size_t)(m + 1) * 4096 + cb + tid * 2]) =
            make_float2(o2, o3);
    }
}

extern "C" void kernel_launch(void* const* d_in, const int* in_sizes, int n_in,
                              void* d_out, int out_size) {
    const float* x = (const float*)d_in[0];
    const float* A = (const float*)d_in[1];
    const float* B = (const float*)d_in[2];
    float*       y = (float*)d_out;

    k1_xa<<<MROWS / BM1, 256>>>(x, A);
    k2_by<<<(MROWS / RB) * (OUT_F / CBT), 256>>>(B, y);
}